// round 17
// baseline (speedup 1.0000x reference)
// R17 resubmission: R14-R16 never ran (broker acquisition timeouts, infra
// failures #10-#12). Body byte-identical: barrier-free warp-skew pipeline;
// shfl_up intra-warp, 32-deep boundary ring + release/acquire seq across
// warps, warp 0 drives cp.async row prefetch. All paper audits complete;
// awaiting first execution on hardware.
#include <cuda_runtime.h>
#include <cstdint>

#define BB 64
#define TT 2000
#define VV 256
#define SS 400
#define NTH 416           // 13 warps, one (even,odd) state pair per thread
#define NW  13
#define ENEG (-(1 << 29)) // exponent marker for zero states
#define SKIPOFF (-(1 << 28))

// Scratch (device globals: no allocation allowed)
__device__ float g_P[(size_t)BB * TT * VV];   // exp(log_probs), 131 MB
__device__ float g_loss[BB];

// ---------------------------------------------------------------------------
// Packed f32x2 exp helper (exp_kernel measured at LTS cap, ~36us: leave alone)
// ---------------------------------------------------------------------------
__device__ __forceinline__ unsigned long long pk2(float lo, float hi) {
    unsigned long long r;
    asm("mov.b64 %0, {%1, %2};" : "=l"(r) : "f"(lo), "f"(hi));
    return r;
}
__device__ __forceinline__ void upk2(unsigned long long v, float& lo, float& hi) {
    asm("mov.b64 {%0, %1}, %2;" : "=f"(lo), "=f"(hi) : "l"(v));
}

__device__ __forceinline__ void exp_pair(float x0, float x1, float& r0, float& r1) {
    x0 = fmaxf(x0, -87.0f);
    x1 = fmaxf(x1, -87.0f);
    unsigned long long x = pk2(x0, x1);
    const unsigned long long L2E  = pk2(1.4426950408889634f, 1.4426950408889634f);
    const unsigned long long MAG  = pk2(12582912.0f, 12582912.0f);   // 1.5 * 2^23
    const unsigned long long NMAG = pk2(-12582912.0f, -12582912.0f);
    const unsigned long long NONE = pk2(-1.0f, -1.0f);
    const unsigned long long C4 = pk2(0.00961812911f, 0.00961812911f);
    const unsigned long long C3 = pk2(0.05550410866f, 0.05550410866f);
    const unsigned long long C2 = pk2(0.24022650696f, 0.24022650696f);
    const unsigned long long C1 = pk2(0.69314718056f, 0.69314718056f);
    const unsigned long long ONE = pk2(1.0f, 1.0f);

    unsigned long long y, z, fi, f, p;
    asm("mul.rn.f32x2 %0, %1, %2;"     : "=l"(y)  : "l"(x),  "l"(L2E));
    asm("add.rn.f32x2 %0, %1, %2;"     : "=l"(z)  : "l"(y),  "l"(MAG));   // round to int
    asm("add.rn.f32x2 %0, %1, %2;"     : "=l"(fi) : "l"(z),  "l"(NMAG));  // i as float
    asm("fma.rn.f32x2 %0, %1, %2, %3;" : "=l"(f)  : "l"(fi), "l"(NONE), "l"(y)); // f = y - i
    asm("fma.rn.f32x2 %0, %1, %2, %3;" : "=l"(p)  : "l"(f), "l"(C4), "l"(C3));
    asm("fma.rn.f32x2 %0, %1, %2, %3;" : "=l"(p)  : "l"(f), "l"(p),  "l"(C2));
    asm("fma.rn.f32x2 %0, %1, %2, %3;" : "=l"(p)  : "l"(f), "l"(p),  "l"(C1));
    asm("fma.rn.f32x2 %0, %1, %2, %3;" : "=l"(p)  : "l"(f), "l"(p),  "l"(ONE));

    float pf0, pf1, zf0, zf1;
    upk2(p, pf0, pf1);
    upk2(z, zf0, zf1);
    r0 = __uint_as_float(__float_as_uint(pf0) + (__float_as_uint(zf0) << 23));
    r1 = __uint_as_float(__float_as_uint(pf1) + (__float_as_uint(zf1) << 23));
}

__global__ void exp_kernel(const float* __restrict__ lp) {
    const float4* in  = (const float4*)lp;
    float4*       out = (float4*)g_P;
    const int64_t n4 = (int64_t)BB * TT * VV / 4;
    int64_t i  = (int64_t)blockIdx.x * blockDim.x + threadIdx.x;
    int64_t st = (int64_t)gridDim.x * blockDim.x;
    for (; i < n4; i += st) {
        float4 v = in[i];
        float4 r;
        exp_pair(v.x, v.y, r.x, r.y);   // FMA/ALU pipes
        r.z = __expf(v.z);              // MUFU pipe
        r.w = __expf(v.w);              // MUFU pipe
        out[i] = r;
    }
}

// ---------------------------------------------------------------------------
// smem release/acquire helpers (memory clobber pins ordering vs plain LDS/STS)
// ---------------------------------------------------------------------------
__device__ __forceinline__ int ld_acq(unsigned a) {
    int v;
    asm volatile("ld.acquire.cta.shared.b32 %0, [%1];" : "=r"(v) : "r"(a) : "memory");
    return v;
}
__device__ __forceinline__ void st_rel(unsigned a, int v) {
    asm volatile("st.release.cta.shared.b32 [%0], %1;" :: "r"(a), "r"(v) : "memory");
}

// 2^d for d <= 0 with exact-zero cutoff below -127
__device__ __forceinline__ float sc2(int d) {
    d = max(d, -127);
    return __int_as_float((d + 127) << 23);
}

// ---------------------------------------------------------------------------
// Kernel 2: CTC forward, extended-range fp32, warp-skew pipeline (no per-step
// CTA barrier). Thread i owns pair (lo=2i blank, hi=2i+1 symbol) in registers.
// ---------------------------------------------------------------------------
__global__ __launch_bounds__(NTH, 1) void ctc_kernel(const int* __restrict__ targets,
                                                     const int* __restrict__ in_len,
                                                     const int* __restrict__ tg_len) {
    __shared__ __align__(16) float prow[32][VV];   // 32-row ring, 32 KB
    __shared__ float2 bnd[NW][32];                 // warp-boundary hi ring
    __shared__ int    seqs[NW];                    // last step published per warp
    __shared__ int    row_ready;                   // rows <= row_ready are loaded
    __shared__ float2 scr[2];

    const int b    = blockIdx.x;
    const int tid  = threadIdx.x;
    const int i    = tid;
    const int lane = tid & 31;
    const int w    = tid >> 5;
    const int tlen = tg_len[b];
    const int ilen = in_len[b];
    const bool act_lo = (i <= tlen);
    const bool act_hi = (i <  tlen);

    int ext = 1, skipbias = SKIPOFF;
    if (i < SS) {
        ext = targets[b * SS + i];
        int prev = (i >= 1) ? targets[b * SS + i - 1] : -1;
        if (ext != prev) skipbias = 0;
    }

    if (tid < NW) seqs[tid] = -1;
    if (tid == 0) row_ready = 8;

    const float* Pb = g_P + (size_t)b * TT * VV;

    // preload rows 0..8 (9 rows x 64 float4) cooperatively
    for (int k = tid; k < 9 * 64; k += NTH) {
        int r = k >> 6, c = k & 63;
        ((float4*)prow[r])[c] = ((const float4*)(Pb + (size_t)r * VV))[c];
    }
    __syncthreads();   // publishes preload + seq/row_ready init

    // t = 0 init
    float m_lo = 0.0f, m_hi = 0.0f;
    int   e_lo = ENEG,  e_hi = ENEG;
    if (i == 0) {
        unsigned pb = __float_as_uint(prow[0][1]);
        e_lo = (int)(pb >> 23) - 127;
        m_lo = __uint_as_float((pb & 0x007FFFFFu) | 0x3F800000u);
        unsigned ph = __float_as_uint(prow[0][ext]);
        e_hi = (int)(ph >> 23) - 127;
        m_hi = __uint_as_float((ph & 0x007FFFFFu) | 0x3F800000u);
    }

    unsigned sb_prow = (unsigned)__cvta_generic_to_shared(&prow[0][0]);
    unsigned sb_seq  = (unsigned)__cvta_generic_to_shared(&seqs[0]);
    unsigned sb_rr   = (unsigned)__cvta_generic_to_shared(&row_ready);

    // publish step-0 boundary (zero-state for all warps except warp 0's pair31)
    if (lane == 31) {
        bnd[w][0] = make_float2(m_hi, __int_as_float(e_hi));
        st_rel(sb_seq + w * 4, 0);
    }

    for (int t = 1; t < ilen; ++t) {
        if (w == 0) {
            // row-ring reuse backpressure: keep warp 12 within 14 steps
            if ((t & 7) == 1 && t > 16) { while (ld_acq(sb_seq + 12 * 4) < t - 14) {} }
            int rp = t + 8;
            if (rp < ilen) {
                unsigned dst = sb_prow + (unsigned)(((rp & 31) * VV + lane * 4) * 4);
                const float* src = Pb + (size_t)rp * VV + lane * 4;
                asm volatile("cp.async.cg.shared.global [%0], [%1], 16;" :: "r"(dst), "l"(src));
                asm volatile("cp.async.cg.shared.global [%0], [%1], 16;"
                             :: "r"(dst + 512), "l"(src + 128));
            }
            asm volatile("cp.async.commit_group;");
            asm volatile("cp.async.wait_group 7;" ::: "memory");  // rows <= t+1 done
            if (lane == 0) st_rel(sb_rr, t + 1);
        } else {
            while (ld_acq(sb_rr) < t) {}        // broadcast spin, steady: 1 poll
        }

        // left-neighbor hi at t-1: shfl within warp, smem ring across warps
        float2 bv = make_float2(0.0f, __int_as_float(ENEG));
        if (w > 0) {
            while (ld_acq(sb_seq + (w - 1) * 4) < t - 1) {}
            bv = bnd[w - 1][(t - 1) & 31];
        }
        float nm1f = __shfl_up_sync(0xffffffffu, m_hi, 1);
        int   ne1i = __shfl_up_sync(0xffffffffu, e_hi, 1);
        float m1 = (lane == 0) ? bv.x : nm1f;
        int   e1 = (lane == 0) ? __float_as_int(bv.y) : ne1i;

        // boundary-ring reuse backpressure (producer side), every 16 steps
        if (w < NW - 1 && (t & 15) == 1 && t > 16) {
            while (ld_acq(sb_seq + (w + 1) * 4) < t - 16) {}
        }

        const float* rowp = prow[t & 31];
        float p_b = rowp[1];
        float p_s = rowp[ext];

        // ---- lo (blank, 2-term: own + left odd neighbor) ----
        int   emx = max(e_lo, e1);
        float s   = fmaf(m_lo, sc2(e_lo - emx), m1 * sc2(e1 - emx)) * p_b;
        unsigned sb = __float_as_uint(s);
        int   nel = emx + (int)(sb >> 23) - 127;
        float nml = __uint_as_float((sb & 0x007FFFFFu) | 0x3F800000u);
        bool  zl  = (s == 0.0f) || !act_lo;

        // ---- hi (symbol, 3-term: own + own-lo + left odd neighbor w/ skip) ----
        int   e2  = e1 + skipbias;
        int   emh = max(e_hi, max(e_lo, e2));
        float sh  = fmaf(m_hi, sc2(e_hi - emh),
                    fmaf(m_lo, sc2(e_lo - emh), m1 * sc2(e2 - emh))) * p_s;
        unsigned sbh = __float_as_uint(sh);
        int   neh = emh + (int)(sbh >> 23) - 127;
        float nmh = __uint_as_float((sbh & 0x007FFFFFu) | 0x3F800000u);
        bool  zh  = (sh == 0.0f) || !act_hi;

        m_lo = zl ? 0.0f : nml;  e_lo = zl ? ENEG : nel;
        m_hi = zh ? 0.0f : nmh;  e_hi = zh ? ENEG : neh;

        if (lane == 31) {
            bnd[w][t & 31] = make_float2(m_hi, __int_as_float(e_hi));
            st_rel(sb_seq + w * 4, t);
        }
    }

    if (w == 0) asm volatile("cp.async.wait_group 0;" ::: "memory");  // drain

    // readout: alpha[2tlen] = lo of pair tlen; alpha[2tlen-1] = hi of pair tlen-1
    if (i == tlen)     scr[0] = make_float2(m_lo, __int_as_float(e_lo));
    if (i == tlen - 1) scr[1] = make_float2(m_hi, __int_as_float(e_hi));
    __syncthreads();

    if (tid == 0) {
        float2 va = scr[0];
        float2 vb = scr[1];
        int ea = __float_as_int(va.y), eb = __float_as_int(vb.y);
        int em = max(ea, eb);
        double ssum = (double)va.x * exp2((double)(ea - em))
                    + (double)vb.x * exp2((double)(eb - em));
        double ll = log(ssum) + (double)em * 0.6931471805599453;
        float loss = (float)(-ll);
        if (!(loss < 1e29f)) loss = 0.0f;      // infeasible guard (matches reference)
        g_loss[b] = loss / (float)tlen;
    }
}

// ---------------------------------------------------------------------------
// Kernel 3: deterministic fixed-tree mean over 64 losses.
// ---------------------------------------------------------------------------
__global__ void finalize_kernel(float* __restrict__ out) {
    int lane = threadIdx.x;
    float v = g_loss[lane] + g_loss[lane + 32];
    v += __shfl_xor_sync(0xffffffffu, v, 16);
    v += __shfl_xor_sync(0xffffffffu, v, 8);
    v += __shfl_xor_sync(0xffffffffu, v, 4);
    v += __shfl_xor_sync(0xffffffffu, v, 2);
    v += __shfl_xor_sync(0xffffffffu, v, 1);
    if (lane == 0) out[0] = v * (1.0f / (float)BB);
}

extern "C" void kernel_launch(void* const* d_in, const int* in_sizes, int n_in,
                              void* d_out, int out_size) {
    const float* lp = (const float*)d_in[0];
    const int*   tg = (const int*)d_in[1];
    const int*   il = (const int*)d_in[2];
    const int*   tl = (const int*)d_in[3];

    exp_kernel<<<3072, 256>>>(lp);
    ctc_kernel<<<BB, NTH>>>(tg, il, tl);
    finalize_kernel<<<1, 32>>>((float*)d_out);
}